// round 4
// baseline (speedup 1.0000x reference)
#include <cuda_runtime.h>
#include <cstdint>

#define NROWS 8192
#define NCOLS 2048
#define ORDER 8
#define NB    148
#define TPB   512
#define MAXR  56

// ---------- packed-f32 primitives (FFMA2 exists on sm_103a via PTX only) ----
__device__ __forceinline__ unsigned long long pack2(float lo, float hi) {
    unsigned long long r;
    asm("mov.b64 %0, {%1, %2};" : "=l"(r) : "f"(lo), "f"(hi));
    return r;
}
__device__ __forceinline__ float2 unpack2(unsigned long long v) {
    float2 f;
    asm("mov.b64 {%0, %1}, %2;" : "=f"(f.x), "=f"(f.y) : "l"(v));
    return f;
}
__device__ __forceinline__ unsigned long long ffma2(
    unsigned long long a, unsigned long long b, unsigned long long c) {
    unsigned long long d;
    asm("fma.rn.f32x2 %0, %1, %2, %3;" : "=l"(d) : "l"(a), "l"(b), "l"(c));
    return d;
}
__device__ __forceinline__ unsigned long long fmul2(
    unsigned long long a, unsigned long long b) {
    unsigned long long d;
    asm("mul.rn.f32x2 %0, %1, %2;" : "=l"(d) : "l"(a), "l"(b));
    return d;
}

__global__ void __launch_bounds__(TPB, 1) orth_fused(
    const float* __restrict__ x, const float* __restrict__ v,
    const float* __restrict__ d, const float* __restrict__ bias,
    float* __restrict__ y)
{
    __shared__ float asum[16 * MAXR * 8];   // [warp][row][k]  28672 B
    __shared__ float bsh[MAXR * 8];         // b per (row,k)
    __shared__ float Tneg[64];              // -(rn_i T_ik rn_k)

    const int t = threadIdx.x, lane = t & 31, w = t >> 5;
    const int c0 = t * 4;

    // ---- load per-thread V slice + d + bias ----
    float4 Vf[ORDER];
#pragma unroll
    for (int k = 0; k < ORDER; ++k)
        Vf[k] = *reinterpret_cast<const float4*>(v + k * NCOLS + c0);
    const float4 d4  = *reinterpret_cast<const float4*>(d + c0);
    const float4 bs4 = *reinterpret_cast<const float4*>(bias + c0);
    const unsigned long long d01 = pack2(d4.x, d4.y),  d23 = pack2(d4.z, d4.w);
    const unsigned long long b01 = pack2(bs4.x, bs4.y), b23 = pack2(bs4.z, bs4.w);

    // ================= Prologue: Gram -> Tneg =================
    {
        float* gpart = asum;  // reuse smem: [warp][40], 36 used
        float G[36];
        int idx = 0;
#pragma unroll
        for (int i = 0; i < ORDER; ++i)
#pragma unroll
            for (int k = i; k < ORDER; ++k) {
                float s = Vf[i].x * Vf[k].x;
                s = fmaf(Vf[i].y, Vf[k].y, s);
                s = fmaf(Vf[i].z, Vf[k].z, s);
                s = fmaf(Vf[i].w, Vf[k].w, s);
                G[idx++] = s;
            }
#pragma unroll
        for (int e = 0; e < 36; ++e) {
#pragma unroll
            for (int m = 16; m >= 1; m >>= 1)
                G[e] += __shfl_xor_sync(0xffffffffu, G[e], m);
        }
        if (lane == 0) {
#pragma unroll
            for (int e = 0; e < 36; ++e) gpart[w * 40 + e] = G[e];
        }
        __syncthreads();
        if (t < 36) {
            float s = 0.f;
#pragma unroll
            for (int ww = 0; ww < 16; ++ww) s += gpart[ww * 40 + t];
            bsh[t] = s;  // park the 36 Gram entries temporarily
        }
        __syncthreads();
        if (t == 0) {
            float Gs[ORDER][ORDER];
            int id2 = 0;
            for (int i = 0; i < ORDER; ++i)
                for (int k = i; k < ORDER; ++k) {
                    Gs[i][k] = bsh[id2]; Gs[k][i] = bsh[id2]; ++id2;
                }
            float rn[ORDER];
            for (int i = 0; i < ORDER; ++i) rn[i] = 1.0f / sqrtf(Gs[i][i]);
            float T[ORDER][ORDER];
            for (int i = 0; i < ORDER; ++i)
                for (int k = 0; k < ORDER; ++k) T[i][k] = 0.f;
            for (int i = 0; i < ORDER; ++i) T[i][i] = 2.f;
            for (int c = 1; c < ORDER; ++c)
                for (int r = 0; r < c; ++r) {
                    float s = 0.f;
                    for (int m = r; m < c; ++m)
                        s += T[r][m] * (Gs[m][c] * rn[m] * rn[c]);
                    T[r][c] = -2.f * s;
                }
            // fold normalization AND the minus sign of the correction
            for (int i = 0; i < ORDER; ++i)
                for (int k = 0; k < ORDER; ++k)
                    Tneg[i * 8 + k] = -(rn[i] * T[i][k] * rn[k]);
        }
    }

    // ---- repack V into f32x2 pairs ----
    unsigned long long V01[ORDER], V23[ORDER];
#pragma unroll
    for (int k = 0; k < ORDER; ++k) {
        V01[k] = pack2(Vf[k].x, Vf[k].y);
        V23[k] = pack2(Vf[k].z, Vf[k].w);
    }
    __syncthreads();

    // ---- row range for this block ----
    const int bid = blockIdx.x;
    const int nr = (bid < 52) ? 56 : 55;
    const int r0 = (bid < 52) ? bid * 56 : 52 * 56 + (bid - 52) * 55;
    const float* xp = x + c0;
    float*       yp = y + c0;

    // ================= Pass A: dot partials for all rows (no barriers) ===
#pragma unroll 4
    for (int j = 0; j < nr; ++j) {
        const float4 xv = *reinterpret_cast<const float4*>(xp + (size_t)(r0 + j) * NCOLS);
        const unsigned long long x01 = pack2(xv.x, xv.y);
        const unsigned long long x23 = pack2(xv.z, xv.w);
        float p[8];
#pragma unroll
        for (int k = 0; k < 8; ++k) {
            const float2 f = unpack2(ffma2(x01, V01[k], fmul2(x23, V23[k])));
            p[k] = f.x + f.y;
        }
        // folded butterfly: 23 shfl, lanes 0..7 end with sum for k = lane
#pragma unroll
        for (int k = 0; k < 8; ++k) {
            p[k] += __shfl_xor_sync(0xffffffffu, p[k], 16);
            p[k] += __shfl_xor_sync(0xffffffffu, p[k], 8);
        }
        {
            const bool h4 = (lane & 4) != 0;
            float q[4];
#pragma unroll
            for (int jj = 0; jj < 4; ++jj) {
                float keep = h4 ? p[jj + 4] : p[jj];
                float send = h4 ? p[jj] : p[jj + 4];
                q[jj] = keep + __shfl_xor_sync(0xffffffffu, send, 4);
            }
            const bool h2 = (lane & 2) != 0;
            float r2[2];
#pragma unroll
            for (int jj = 0; jj < 2; ++jj) {
                float keep = h2 ? q[jj + 2] : q[jj];
                float send = h2 ? q[jj] : q[jj + 2];
                r2[jj] = keep + __shfl_xor_sync(0xffffffffu, send, 2);
            }
            const bool h1 = (lane & 1) != 0;
            float keep = h1 ? r2[1] : r2[0];
            float send = h1 ? r2[0] : r2[1];
            float s = keep + __shfl_xor_sync(0xffffffffu, send, 1);
            if (lane < 8) asum[(w * MAXR + j) * 8 + lane] = s;
        }
    }
    __syncthreads();

    // ================= Pass B: cross-warp reduce + T' (448 thr) ==========
    if (t < MAXR * 8) {   // 14 full warps -> safe shfl masks
        const int row = t >> 3, k = t & 7;
        float a = 0.f;
#pragma unroll
        for (int ww = 0; ww < 16; ++ww) a += asum[(ww * MAXR + row) * 8 + k];
        float bk = 0.f;
#pragma unroll
        for (int i = 0; i < 8; ++i) {
            const float ai = __shfl_sync(0xffffffffu, a, (lane & 24) | i);
            bk = fmaf(ai, Tneg[i * 8 + k], bk);
        }
        bsh[row * 8 + k] = bk;
    }
    __syncthreads();

    // ================= Pass C: correction + scale + store ================
#pragma unroll 4
    for (int j = 0; j < nr; ++j) {
        const float4 xv = __ldcs(reinterpret_cast<const float4*>(xp + (size_t)(r0 + j) * NCOLS));
        const float4 c0v = *reinterpret_cast<const float4*>(&bsh[j * 8]);
        const float4 c1v = *reinterpret_cast<const float4*>(&bsh[j * 8 + 4]);
        unsigned long long bb[8];
        bb[0] = pack2(c0v.x, c0v.x); bb[1] = pack2(c0v.y, c0v.y);
        bb[2] = pack2(c0v.z, c0v.z); bb[3] = pack2(c0v.w, c0v.w);
        bb[4] = pack2(c1v.x, c1v.x); bb[5] = pack2(c1v.y, c1v.y);
        bb[6] = pack2(c1v.z, c1v.z); bb[7] = pack2(c1v.w, c1v.w);

        unsigned long long a01 = pack2(xv.x, xv.y);
        unsigned long long a23 = pack2(xv.z, xv.w);
#pragma unroll
        for (int k = 0; k < 8; ++k) {
            a01 = ffma2(bb[k], V01[k], a01);   // Tneg already carries the minus
            a23 = ffma2(bb[k], V23[k], a23);
        }
        a01 = ffma2(a01, d01, b01);
        a23 = ffma2(a23, d23, b23);
        const float2 o0 = unpack2(a01), o1 = unpack2(a23);
        __stcs(reinterpret_cast<float4*>(yp + (size_t)(r0 + j) * NCOLS),
               make_float4(o0.x, o0.y, o1.x, o1.y));
    }
}

extern "C" void kernel_launch(void* const* d_in, const int* in_sizes, int n_in,
                              void* d_out, int out_size) {
    const float* x    = (const float*)d_in[0];
    const float* v    = (const float*)d_in[1];
    const float* dvec = (const float*)d_in[2];
    const float* bias = (const float*)d_in[3];
    float* y = (float*)d_out;
    (void)in_sizes; (void)n_in; (void)out_size;

    orth_fused<<<NB, TPB>>>(x, v, dvec, bias, y);
}